// round 1
// baseline (speedup 1.0000x reference)
#include <cuda_runtime.h>
#include <math.h>

// Problem constants
constexpr int cN0   = 300000;
constexpr int cN1   = 60000;
constexpr int cN2   = 6000;
constexpr int cE1   = 1200000;
constexpr int cE2   = 300000;
constexpr int cR    = 4;
constexpr int cDIN  = 128;
constexpr int cDH   = 128;
constexpr int cDOUT = 64;
constexpr float cEPS = 1e-5f;

// Scratch (static device globals; no allocation allowed)
__device__ __align__(256) float g_h[cN1 * cDH];          // layer-1 output / layer-2 input (raw, pre-BN)
__device__ __align__(256) float g_agg2[cR * cN2 * cDH];  // layer-2 per-relation aggregates
__device__ float g_sum[cDH];
__device__ float g_sumsq[cDH];
__device__ float g_scale[cDH];
__device__ float g_shift[cDH];
__device__ int   g_qcount;
__device__ int   g_queue[cE1];   // worst-case safe queue of layer-1 edges needing compute

// ---------------------------------------------------------------------------
// K1: zero scratch
__global__ void k_zero() {
    int idx = blockIdx.x * blockDim.x + threadIdx.x;
    int stride = gridDim.x * blockDim.x;
    const int n = cR * cN2 * cDH;
    for (int i = idx; i < n; i += stride) g_agg2[i] = 0.f;
    if (idx < cDH) { g_sum[idx] = 0.f; g_sumsq[idx] = 0.f; }
    if (idx == 0) g_qcount = 0;
}

// ---------------------------------------------------------------------------
// K2: history fill. Valid nodes: copy history row. Invalid nodes (rare):
// initialize with self-loop  x[n] @ Wself1 + b1  (edge messages added later).
__global__ void k_fill(const float* __restrict__ x, const int* __restrict__ hmap,
                       const float* __restrict__ hbuf, const float* __restrict__ Wself1,
                       const float* __restrict__ b1) {
    int gt = blockIdx.x * blockDim.x + threadIdx.x;
    int wid = gt >> 5, lane = gt & 31;
    int nw = (gridDim.x * blockDim.x) >> 5;
    for (int n = wid; n < cN1; n += nw) {
        int m = hmap[n];
        float4* dstp = reinterpret_cast<float4*>(g_h + (size_t)n * cDH);
        if (m >= 0) {
            const float4* srcp = reinterpret_cast<const float4*>(hbuf + (size_t)m * cDH);
            dstp[lane] = srcp[lane];
        } else {
            int o = lane * 4;
            float a0 = b1[o], a1 = b1[o + 1], a2 = b1[o + 2], a3 = b1[o + 3];
            const float* xr = x + (size_t)n * cDIN;
            for (int i = 0; i < cDIN; i++) {
                float xv = xr[i];
                float4 w = reinterpret_cast<const float4*>(Wself1 + (size_t)i * cDH)[lane];
                a0 += xv * w.x; a1 += xv * w.y; a2 += xv * w.z; a3 += xv * w.w;
            }
            float4 v; v.x = a0; v.y = a1; v.z = a2; v.w = a3;
            dstp[lane] = v;
        }
    }
}

// ---------------------------------------------------------------------------
// K3a: scan all E1 edges, queue the (rare) ones whose dst has no cached history.
__global__ void k_scan1(const int* __restrict__ dst1, const int* __restrict__ hmap) {
    int idx = blockIdx.x * blockDim.x + threadIdx.x;
    int stride = gridDim.x * blockDim.x;
    for (int e = idx; e < cE1; e += stride) {
        int d = dst1[e];
        if (hmap[d] < 0) {
            int pos = atomicAdd(&g_qcount, 1);
            g_queue[pos] = e;
        }
    }
}

// K3b: process queued edges: h[dst] += x[src] @ W1[et]. One warp per edge.
__global__ void k_edge1(const float* __restrict__ x, const int* __restrict__ src1,
                        const int* __restrict__ dst1, const int* __restrict__ et1,
                        const float* __restrict__ W1) {
    int gt = blockIdx.x * blockDim.x + threadIdx.x;
    int wid = gt >> 5, lane = gt & 31;
    int nw = (gridDim.x * blockDim.x) >> 5;
    int cnt = g_qcount;
    for (int q = wid; q < cnt; q += nw) {
        int e = g_queue[q];
        int s = src1[e], d = dst1[e], r = et1[e];
        const float* xr = x + (size_t)s * cDIN;
        const float* W = W1 + (size_t)r * cDIN * cDH;
        int o = lane * 4;
        float a0 = 0.f, a1 = 0.f, a2 = 0.f, a3 = 0.f;
        for (int i = 0; i < cDIN; i++) {
            float xv = xr[i];
            float4 w = *reinterpret_cast<const float4*>(W + (size_t)i * cDH + o);
            a0 += xv * w.x; a1 += xv * w.y; a2 += xv * w.z; a3 += xv * w.w;
        }
        float* hp = g_h + (size_t)d * cDH + o;
        atomicAdd(hp + 0, a0);
        atomicAdd(hp + 1, a1);
        atomicAdd(hp + 2, a2);
        atomicAdd(hp + 3, a3);
    }
}

// ---------------------------------------------------------------------------
// K4: per-column BN statistics over all N1 rows of h.
__global__ void k_stats() {
    __shared__ float ssum[4][cDH];
    __shared__ float ssq[4][cDH];
    int c = threadIdx.x;        // 0..127
    int ty = threadIdx.y;       // 0..3
    float s = 0.f, sq = 0.f;
    int stride = gridDim.x * 4;
    for (int n = blockIdx.x * 4 + ty; n < cN1; n += stride) {
        float v = g_h[(size_t)n * cDH + c];
        s += v; sq += v * v;
    }
    ssum[ty][c] = s; ssq[ty][c] = sq;
    __syncthreads();
    if (ty == 0) {
        for (int k = 1; k < 4; k++) { s += ssum[k][c]; sq += ssq[k][c]; }
        atomicAdd(&g_sum[c], s);
        atomicAdd(&g_sumsq[c], sq);
    }
}

// K5: finalize BN affine: normalized = h * scale + shift
__global__ void k_bnfinal(const float* __restrict__ gamma, const float* __restrict__ beta) {
    int c = threadIdx.x;
    float mean = g_sum[c] * (1.f / cN1);
    float var = g_sumsq[c] * (1.f / cN1) - mean * mean;
    float inv = rsqrtf(var + cEPS);
    float sc = inv * gamma[c];
    g_scale[c] = sc;
    g_shift[c] = beta[c] - mean * sc;
}

// ---------------------------------------------------------------------------
// K6: layer-2 scatter. One warp per edge: gather h[src], apply BN+relu on the
// fly, reduce into agg2[et][dst] with vectorized red.global.add.v4.f32.
__global__ void k_scatter2(const int* __restrict__ src2, const int* __restrict__ dst2,
                           const int* __restrict__ et2) {
    int gt = blockIdx.x * blockDim.x + threadIdx.x;
    int wid = gt >> 5, lane = gt & 31;
    int nw = (gridDim.x * blockDim.x) >> 5;
    float4 sc = reinterpret_cast<const float4*>(g_scale)[lane];
    float4 sh = reinterpret_cast<const float4*>(g_shift)[lane];
    for (int e = wid; e < cE2; e += nw) {
        int s = src2[e], d = dst2[e], r = et2[e];
        float4 hv = reinterpret_cast<const float4*>(g_h + (size_t)s * cDH)[lane];
        float y0 = fmaxf(hv.x * sc.x + sh.x, 0.f);
        float y1 = fmaxf(hv.y * sc.y + sh.y, 0.f);
        float y2 = fmaxf(hv.z * sc.z + sh.z, 0.f);
        float y3 = fmaxf(hv.w * sc.w + sh.w, 0.f);
        float* p = g_agg2 + ((size_t)r * cN2 + d) * cDH + lane * 4;
        asm volatile("red.global.add.v4.f32 [%0], {%1, %2, %3, %4};"
                     :: "l"(p), "f"(y0), "f"(y1), "f"(y2), "f"(y3) : "memory");
    }
}

// ---------------------------------------------------------------------------
// K7: out[d] = sum_r agg2[r,d] @ W2[r] + relu(bn(h[d])) @ Wself2 + b2
// 16 dst nodes per block, 256 threads = 64 output cols x 4 dst-groups.
constexpr int TD = 16;
__global__ void k_out(const float* __restrict__ W2, const float* __restrict__ Wself2,
                      const float* __restrict__ b2, float* __restrict__ out) {
    __shared__ __align__(16) float s_agg[cR * TD * cDH];  // [r][dl][i]
    __shared__ __align__(16) float s_hn[TD * cDH];        // [dl][i]
    int d0 = blockIdx.x * TD;
    int tid = threadIdx.x;

    for (int idx = tid; idx < cR * TD * cDH; idx += blockDim.x) {
        int r = idx / (TD * cDH);
        int rem = idx - r * (TD * cDH);
        int dl = rem / cDH;
        int i = rem - dl * cDH;
        s_agg[idx] = g_agg2[((size_t)r * cN2 + d0 + dl) * cDH + i];
    }
    for (int idx = tid; idx < TD * cDH; idx += blockDim.x) {
        int dl = idx / cDH;
        int i = idx - dl * cDH;
        float v = g_h[(size_t)(d0 + dl) * cDH + i];
        s_hn[idx] = fmaxf(v * g_scale[i] + g_shift[i], 0.f);
    }
    __syncthreads();

    int o = tid & 63;
    int dg = tid >> 6;   // 0..3, handles dl = dg*4 .. dg*4+3
    float bo = b2[o];
    float acc[4] = {bo, bo, bo, bo};

    #pragma unroll
    for (int r = 0; r < cR; r++) {
        const float* W = W2 + ((size_t)r * cDH) * cDOUT + o;
        const float4* A = reinterpret_cast<const float4*>(s_agg + (r * TD + dg * 4) * cDH);
        #pragma unroll 4
        for (int i4 = 0; i4 < cDH / 4; i4++) {
            float w0 = W[(i4 * 4 + 0) * cDOUT];
            float w1 = W[(i4 * 4 + 1) * cDOUT];
            float w2 = W[(i4 * 4 + 2) * cDOUT];
            float w3 = W[(i4 * 4 + 3) * cDOUT];
            #pragma unroll
            for (int j = 0; j < 4; j++) {
                float4 a = A[j * (cDH / 4) + i4];
                acc[j] += a.x * w0 + a.y * w1 + a.z * w2 + a.w * w3;
            }
        }
    }
    {
        const float* W = Wself2 + o;
        const float4* Hn = reinterpret_cast<const float4*>(s_hn + dg * 4 * cDH);
        #pragma unroll 4
        for (int i4 = 0; i4 < cDH / 4; i4++) {
            float w0 = W[(i4 * 4 + 0) * cDOUT];
            float w1 = W[(i4 * 4 + 1) * cDOUT];
            float w2 = W[(i4 * 4 + 2) * cDOUT];
            float w3 = W[(i4 * 4 + 3) * cDOUT];
            #pragma unroll
            for (int j = 0; j < 4; j++) {
                float4 a = Hn[j * (cDH / 4) + i4];
                acc[j] += a.x * w0 + a.y * w1 + a.z * w2 + a.w * w3;
            }
        }
    }
    #pragma unroll
    for (int j = 0; j < 4; j++)
        out[(size_t)(d0 + dg * 4 + j) * cDOUT + o] = acc[j];
}

// ---------------------------------------------------------------------------
// K8: in-place log-softmax over rows of out [N2, 64]. One warp per row.
__global__ void k_lsm(float* __restrict__ out) {
    int gt = blockIdx.x * blockDim.x + threadIdx.x;
    int wid = gt >> 5, lane = gt & 31;
    int nw = (gridDim.x * blockDim.x) >> 5;
    for (int row = wid; row < cN2; row += nw) {
        float* p = out + (size_t)row * cDOUT;
        float v0 = p[lane], v1 = p[lane + 32];
        float m = fmaxf(v0, v1);
        #pragma unroll
        for (int off = 16; off > 0; off >>= 1)
            m = fmaxf(m, __shfl_xor_sync(0xffffffffu, m, off));
        float s = expf(v0 - m) + expf(v1 - m);
        #pragma unroll
        for (int off = 16; off > 0; off >>= 1)
            s += __shfl_xor_sync(0xffffffffu, s, off);
        float l = m + logf(s);
        p[lane] = v0 - l;
        p[lane + 32] = v1 - l;
    }
}

// ---------------------------------------------------------------------------
extern "C" void kernel_launch(void* const* d_in, const int* in_sizes, int n_in,
                              void* d_out, int out_size) {
    (void)in_sizes; (void)n_in; (void)out_size;
    const float* x      = (const float*)d_in[0];
    const int*   src1   = (const int*)d_in[1];
    const int*   dst1   = (const int*)d_in[2];
    const int*   et1    = (const int*)d_in[3];
    const int*   src2   = (const int*)d_in[4];
    const int*   dst2   = (const int*)d_in[5];
    const int*   et2    = (const int*)d_in[6];
    const int*   hmap   = (const int*)d_in[7];
    const float* hbuf   = (const float*)d_in[8];
    const float* W1     = (const float*)d_in[9];
    const float* Wself1 = (const float*)d_in[10];
    const float* b1     = (const float*)d_in[11];
    const float* gamma  = (const float*)d_in[12];
    const float* beta   = (const float*)d_in[13];
    const float* W2     = (const float*)d_in[14];
    const float* Wself2 = (const float*)d_in[15];
    const float* b2     = (const float*)d_in[16];
    float* out = (float*)d_out;

    k_zero<<<1024, 256>>>();
    k_fill<<<512, 256>>>(x, hmap, hbuf, Wself1, b1);
    k_scan1<<<2048, 256>>>(dst1, hmap);
    k_edge1<<<64, 256>>>(x, src1, dst1, et1, W1);
    k_stats<<<128, dim3(128, 4)>>>();
    k_bnfinal<<<1, 128>>>(gamma, beta);
    k_scatter2<<<2048, 256>>>(src2, dst2, et2);
    k_out<<<cN2 / TD, 256>>>(W2, Wself2, b2, out);
    k_lsm<<<256, 256>>>(out);
}

// round 4
// speedup vs baseline: 1.1075x; 1.1075x over previous
#include <cuda_runtime.h>
#include <math.h>

// Problem constants
constexpr int cN1   = 60000;
constexpr int cN2   = 6000;
constexpr int cE1   = 1200000;
constexpr int cE2   = 300000;
constexpr int cR    = 4;
constexpr int cDIN  = 128;
constexpr int cDH   = 128;
constexpr int cDOUT = 64;
constexpr float cEPS = 1e-5f;

// Scratch (static device globals; no allocation allowed)
__device__ __align__(256) float g_h[cN1 * cDH];          // layer-1 output (raw, pre-BN)
__device__ __align__(256) float g_agg2[cR * cN2 * cDH];  // layer-2 per-relation aggregates
__device__ float g_sum[cDH];
__device__ float g_sumsq[cDH];
__device__ float g_scale[cDH];
__device__ float g_shift[cDH];
__device__ int   g_ncount;
__device__ int   g_nqueue[cN1];  // nodes with no cached history (rare)

// ---------------------------------------------------------------------------
// Warp-cooperative 128x128 matvec with high MLP.
// x row (128 floats) is loaded distributed: lane l holds x[4l..4l+3].
// Lane l returns partial outputs for columns [4l, 4l+4).
__device__ __forceinline__ float4 warp_matvec128(const float* __restrict__ xr,
                                                 const float* __restrict__ W,
                                                 int lane) {
    float4 xl = reinterpret_cast<const float4*>(xr)[lane];
    float a0 = 0.f, a1 = 0.f, a2 = 0.f, a3 = 0.f;
    #pragma unroll 8
    for (int i4 = 0; i4 < 32; i4++) {
        float bx = __shfl_sync(0xffffffffu, xl.x, i4);
        float by = __shfl_sync(0xffffffffu, xl.y, i4);
        float bz = __shfl_sync(0xffffffffu, xl.z, i4);
        float bw = __shfl_sync(0xffffffffu, xl.w, i4);
        float4 w0 = reinterpret_cast<const float4*>(W + (size_t)(i4 * 4 + 0) * cDH)[lane];
        float4 w1 = reinterpret_cast<const float4*>(W + (size_t)(i4 * 4 + 1) * cDH)[lane];
        float4 w2 = reinterpret_cast<const float4*>(W + (size_t)(i4 * 4 + 2) * cDH)[lane];
        float4 w3 = reinterpret_cast<const float4*>(W + (size_t)(i4 * 4 + 3) * cDH)[lane];
        a0 += bx * w0.x + by * w1.x + bz * w2.x + bw * w3.x;
        a1 += bx * w0.y + by * w1.y + bz * w2.y + bw * w3.y;
        a2 += bx * w0.z + by * w1.z + bz * w2.z + bw * w3.z;
        a3 += bx * w0.w + by * w1.w + bz * w2.w + bw * w3.w;
    }
    float4 r; r.x = a0; r.y = a1; r.z = a2; r.w = a3;
    return r;
}

// ---------------------------------------------------------------------------
// K1: zero scratch
__global__ void k_zero() {
    int idx = blockIdx.x * blockDim.x + threadIdx.x;
    int stride = gridDim.x * blockDim.x;
    const int n = cR * cN2 * cDH;
    for (int i = idx; i < n; i += stride) g_agg2[i] = 0.f;
    if (idx < cDH) { g_sum[idx] = 0.f; g_sumsq[idx] = 0.f; }
    if (idx == 0) g_ncount = 0;
}

// ---------------------------------------------------------------------------
// K2: history fill + BN stats for valid rows. Invalid nodes get queued.
__global__ void k_fill(const int* __restrict__ hmap, const float* __restrict__ hbuf) {
    __shared__ float bsum[cDH];
    __shared__ float bsq[cDH];
    int tid = threadIdx.x;
    if (tid < cDH) { bsum[tid] = 0.f; bsq[tid] = 0.f; }
    __syncthreads();
    int gt = blockIdx.x * blockDim.x + tid;
    int wid = gt >> 5, lane = gt & 31;
    int nw = (gridDim.x * blockDim.x) >> 5;
    float s0 = 0.f, s1 = 0.f, s2 = 0.f, s3 = 0.f;
    float q0 = 0.f, q1 = 0.f, q2 = 0.f, q3 = 0.f;
    for (int n = wid; n < cN1; n += nw) {
        int m = hmap[n];
        if (m >= 0) {
            float4 v = reinterpret_cast<const float4*>(hbuf + (size_t)m * cDH)[lane];
            reinterpret_cast<float4*>(g_h + (size_t)n * cDH)[lane] = v;
            s0 += v.x; s1 += v.y; s2 += v.z; s3 += v.w;
            q0 += v.x * v.x; q1 += v.y * v.y; q2 += v.z * v.z; q3 += v.w * v.w;
        } else if (lane == 0) {
            int p = atomicAdd(&g_ncount, 1);
            g_nqueue[p] = n;
        }
    }
    int c = lane * 4;
    atomicAdd(&bsum[c + 0], s0); atomicAdd(&bsum[c + 1], s1);
    atomicAdd(&bsum[c + 2], s2); atomicAdd(&bsum[c + 3], s3);
    atomicAdd(&bsq[c + 0], q0);  atomicAdd(&bsq[c + 1], q1);
    atomicAdd(&bsq[c + 2], q2);  atomicAdd(&bsq[c + 3], q3);
    __syncthreads();
    if (tid < cDH) {
        atomicAdd(&g_sum[tid], bsum[tid]);
        atomicAdd(&g_sumsq[tid], bsq[tid]);
    }
}

// ---------------------------------------------------------------------------
// K3: invalid nodes (rare): h[n] = x[n] @ Wself1 + b1, plus their BN stats.
__global__ void k_inv(const float* __restrict__ x, const float* __restrict__ Wself1,
                      const float* __restrict__ b1) {
    int gt = blockIdx.x * blockDim.x + threadIdx.x;
    int wid = gt >> 5, lane = gt & 31;
    int nw = (gridDim.x * blockDim.x) >> 5;
    int cnt = g_ncount;
    float4 bb = reinterpret_cast<const float4*>(b1)[lane];
    for (int q = wid; q < cnt; q += nw) {
        int n = g_nqueue[q];
        float4 a = warp_matvec128(x + (size_t)n * cDIN, Wself1, lane);
        a.x += bb.x; a.y += bb.y; a.z += bb.z; a.w += bb.w;
        reinterpret_cast<float4*>(g_h + (size_t)n * cDH)[lane] = a;
        int c = lane * 4;
        atomicAdd(&g_sum[c + 0], a.x); atomicAdd(&g_sumsq[c + 0], a.x * a.x);
        atomicAdd(&g_sum[c + 1], a.y); atomicAdd(&g_sumsq[c + 1], a.y * a.y);
        atomicAdd(&g_sum[c + 2], a.z); atomicAdd(&g_sumsq[c + 2], a.z * a.z);
        atomicAdd(&g_sum[c + 3], a.w); atomicAdd(&g_sumsq[c + 3], a.w * a.w);
    }
}

// ---------------------------------------------------------------------------
// K4: fused scan + edge processing for layer 1. For the rare edges whose dst
// has no cached history, the whole warp computes msg = x[src] @ W1[et] and
// atomically adds it into g_h[dst]; BN stats are corrected exactly using the
// old value returned by atomicAdd (telescoping: d(sumsq) = 2*old*a + a^2).
__global__ void k_edges1(const float* __restrict__ x, const int* __restrict__ src1,
                         const int* __restrict__ dst1, const int* __restrict__ et1,
                         const int* __restrict__ hmap, const float* __restrict__ W1) {
    int gt = blockIdx.x * blockDim.x + threadIdx.x;
    int wid = gt >> 5, lane = gt & 31;
    int nwarp = (gridDim.x * blockDim.x) >> 5;
    // 32 | cE1, so every warp's 32 lanes are fully in-range together.
    for (int eb = wid * 32; eb < cE1; eb += nwarp * 32) {
        int e = eb + lane;
        int d = dst1[e];
        bool need = (hmap[d] < 0);
        unsigned m = __ballot_sync(0xffffffffu, need);
        while (m) {
            int bit = __ffs(m) - 1; m &= m - 1;
            int ee = eb + bit;
            int dd = __shfl_sync(0xffffffffu, d, bit);
            int ss = src1[ee];   // same-address broadcast load
            int rr = et1[ee];
            float4 a = warp_matvec128(x + (size_t)ss * cDIN,
                                      W1 + (size_t)rr * cDIN * cDH, lane);
            float* hp = g_h + (size_t)dd * cDH + lane * 4;
            float o0 = atomicAdd(hp + 0, a.x);
            float o1 = atomicAdd(hp + 1, a.y);
            float o2 = atomicAdd(hp + 2, a.z);
            float o3 = atomicAdd(hp + 3, a.w);
            int c = lane * 4;
            atomicAdd(&g_sum[c + 0], a.x);
            atomicAdd(&g_sumsq[c + 0], fmaf(2.f * o0, a.x, a.x * a.x));
            atomicAdd(&g_sum[c + 1], a.y);
            atomicAdd(&g_sumsq[c + 1], fmaf(2.f * o1, a.y, a.y * a.y));
            atomicAdd(&g_sum[c + 2], a.z);
            atomicAdd(&g_sumsq[c + 2], fmaf(2.f * o2, a.z, a.z * a.z));
            atomicAdd(&g_sum[c + 3], a.w);
            atomicAdd(&g_sumsq[c + 3], fmaf(2.f * o3, a.w, a.w * a.w));
        }
    }
}

// ---------------------------------------------------------------------------
// K5: finalize BN affine: normalized = h * scale + shift
__global__ void k_bnfinal(const float* __restrict__ gamma, const float* __restrict__ beta) {
    int c = threadIdx.x;
    float mean = g_sum[c] * (1.f / cN1);
    float var = g_sumsq[c] * (1.f / cN1) - mean * mean;
    float inv = rsqrtf(var + cEPS);
    float sc = inv * gamma[c];
    g_scale[c] = sc;
    g_shift[c] = beta[c] - mean * sc;
}

// ---------------------------------------------------------------------------
// K6: layer-2 scatter, 2 edges per warp-iteration for doubled MLP.
// Gather h[src], apply BN+relu on the fly, reduce into agg2[et][dst] with
// vectorized red.global.add.v4.f32.
__global__ void k_scatter2(const int* __restrict__ src2, const int* __restrict__ dst2,
                           const int* __restrict__ et2) {
    int gt = blockIdx.x * blockDim.x + threadIdx.x;
    int wid = gt >> 5, lane = gt & 31;
    int nw = (gridDim.x * blockDim.x) >> 5;
    float4 sc = reinterpret_cast<const float4*>(g_scale)[lane];
    float4 sh = reinterpret_cast<const float4*>(g_shift)[lane];
    // Pair edges (e, e + nw) per iteration for doubled MLP.
    for (int e = wid; e < cE2; e += 2 * nw) {
        int e2 = e + nw;
        bool has2 = (e2 < cE2);
        int sA = src2[e], dA = dst2[e], rA = et2[e];
        int sB = has2 ? src2[e2] : sA;
        int dB = has2 ? dst2[e2] : dA;
        int rB = has2 ? et2[e2] : rA;
        float4 hA = reinterpret_cast<const float4*>(g_h + (size_t)sA * cDH)[lane];
        float4 hB = reinterpret_cast<const float4*>(g_h + (size_t)sB * cDH)[lane];
        float a0 = fmaxf(hA.x * sc.x + sh.x, 0.f);
        float a1 = fmaxf(hA.y * sc.y + sh.y, 0.f);
        float a2 = fmaxf(hA.z * sc.z + sh.z, 0.f);
        float a3 = fmaxf(hA.w * sc.w + sh.w, 0.f);
        float* pA = g_agg2 + ((size_t)rA * cN2 + dA) * cDH + lane * 4;
        asm volatile("red.global.add.v4.f32 [%0], {%1, %2, %3, %4};"
                     :: "l"(pA), "f"(a0), "f"(a1), "f"(a2), "f"(a3) : "memory");
        if (has2) {
            float b0 = fmaxf(hB.x * sc.x + sh.x, 0.f);
            float b1 = fmaxf(hB.y * sc.y + sh.y, 0.f);
            float b2 = fmaxf(hB.z * sc.z + sh.z, 0.f);
            float b3 = fmaxf(hB.w * sc.w + sh.w, 0.f);
            float* pB = g_agg2 + ((size_t)rB * cN2 + dB) * cDH + lane * 4;
            asm volatile("red.global.add.v4.f32 [%0], {%1, %2, %3, %4};"
                         :: "l"(pB), "f"(b0), "f"(b1), "f"(b2), "f"(b3) : "memory");
        }
    }
}

// ---------------------------------------------------------------------------
// K7: out[d] = sum_r agg2[r,d] @ W2[r] + relu(bn(h[d])) @ Wself2 + b2
constexpr int TD = 16;
__global__ void k_out(const float* __restrict__ W2, const float* __restrict__ Wself2,
                      const float* __restrict__ b2, float* __restrict__ out) {
    __shared__ __align__(16) float s_agg[cR * TD * cDH];  // [r][dl][i]
    __shared__ __align__(16) float s_hn[TD * cDH];        // [dl][i]
    int d0 = blockIdx.x * TD;
    int tid = threadIdx.x;

    for (int idx = tid; idx < cR * TD * cDH; idx += blockDim.x) {
        int r = idx / (TD * cDH);
        int rem = idx - r * (TD * cDH);
        int dl = rem / cDH;
        int i = rem - dl * cDH;
        s_agg[idx] = g_agg2[((size_t)r * cN2 + d0 + dl) * cDH + i];
    }
    for (int idx = tid; idx < TD * cDH; idx += blockDim.x) {
        int dl = idx / cDH;
        int i = idx - dl * cDH;
        float v = g_h[(size_t)(d0 + dl) * cDH + i];
        s_hn[idx] = fmaxf(v * g_scale[i] + g_shift[i], 0.f);
    }
    __syncthreads();

    int o = tid & 63;
    int dg = tid >> 6;   // 0..3, handles dl = dg*4 .. dg*4+3
    float bo = b2[o];
    float acc[4] = {bo, bo, bo, bo};

    #pragma unroll
    for (int r = 0; r < cR; r++) {
        const float* W = W2 + ((size_t)r * cDH) * cDOUT + o;
        const float4* A = reinterpret_cast<const float4*>(s_agg + (r * TD + dg * 4) * cDH);
        #pragma unroll 4
        for (int i4 = 0; i4 < cDH / 4; i4++) {
            float w0 = W[(i4 * 4 + 0) * cDOUT];
            float w1 = W[(i4 * 4 + 1) * cDOUT];
            float w2 = W[(i4 * 4 + 2) * cDOUT];
            float w3 = W[(i4 * 4 + 3) * cDOUT];
            #pragma unroll
            for (int j = 0; j < 4; j++) {
                float4 a = A[j * (cDH / 4) + i4];
                acc[j] += a.x * w0 + a.y * w1 + a.z * w2 + a.w * w3;
            }
        }
    }
    {
        const float* W = Wself2 + o;
        const float4* Hn = reinterpret_cast<const float4*>(s_hn + dg * 4 * cDH);
        #pragma unroll 4
        for (int i4 = 0; i4 < cDH / 4; i4++) {
            float w0 = W[(i4 * 4 + 0) * cDOUT];
            float w1 = W[(i4 * 4 + 1) * cDOUT];
            float w2 = W[(i4 * 4 + 2) * cDOUT];
            float w3 = W[(i4 * 4 + 3) * cDOUT];
            #pragma unroll
            for (int j = 0; j < 4; j++) {
                float4 a = Hn[j * (cDH / 4) + i4];
                acc[j] += a.x * w0 + a.y * w1 + a.z * w2 + a.w * w3;
            }
        }
    }
    #pragma unroll
    for (int j = 0; j < 4; j++)
        out[(size_t)(d0 + dg * 4 + j) * cDOUT + o] = acc[j];
}

// ---------------------------------------------------------------------------
// K8: in-place log-softmax over rows of out [N2, 64]. One warp per row.
__global__ void k_lsm(float* __restrict__ out) {
    int gt = blockIdx.x * blockDim.x + threadIdx.x;
    int wid = gt >> 5, lane = gt & 31;
    int nw = (gridDim.x * blockDim.x) >> 5;
    for (int row = wid; row < cN2; row += nw) {
        float* p = out + (size_t)row * cDOUT;
        float v0 = p[lane], v1 = p[lane + 32];
        float m = fmaxf(v0, v1);
        #pragma unroll
        for (int off = 16; off > 0; off >>= 1)
            m = fmaxf(m, __shfl_xor_sync(0xffffffffu, m, off));
        float s = expf(v0 - m) + expf(v1 - m);
        #pragma unroll
        for (int off = 16; off > 0; off >>= 1)
            s += __shfl_xor_sync(0xffffffffu, s, off);
        float l = m + logf(s);
        p[lane] = v0 - l;
        p[lane + 32] = v1 - l;
    }
}

// ---------------------------------------------------------------------------
extern "C" void kernel_launch(void* const* d_in, const int* in_sizes, int n_in,
                              void* d_out, int out_size) {
    (void)in_sizes; (void)n_in; (void)out_size;
    const float* x      = (const float*)d_in[0];
    const int*   src1   = (const int*)d_in[1];
    const int*   dst1   = (const int*)d_in[2];
    const int*   et1    = (const int*)d_in[3];
    const int*   src2   = (const int*)d_in[4];
    const int*   dst2   = (const int*)d_in[5];
    const int*   et2    = (const int*)d_in[6];
    const int*   hmap   = (const int*)d_in[7];
    const float* hbuf   = (const float*)d_in[8];
    const float* W1     = (const float*)d_in[9];
    const float* Wself1 = (const float*)d_in[10];
    const float* b1     = (const float*)d_in[11];
    const float* gamma  = (const float*)d_in[12];
    const float* beta   = (const float*)d_in[13];
    const float* W2     = (const float*)d_in[14];
    const float* Wself2 = (const float*)d_in[15];
    const float* b2     = (const float*)d_in[16];
    float* out = (float*)d_out;

    k_zero<<<1024, 256>>>();
    k_fill<<<256, 256>>>(hmap, hbuf);
    k_inv<<<16, 256>>>(x, Wself1, b1);
    k_edges1<<<1024, 256>>>(x, src1, dst1, et1, hmap, W1);
    k_bnfinal<<<1, 128>>>(gamma, beta);
    k_scatter2<<<2048, 256>>>(src2, dst2, et2);
    k_out<<<cN2 / TD, 256>>>(W2, Wself2, b2, out);
    k_lsm<<<256, 256>>>(out);
}